// round 16
// baseline (speedup 1.0000x reference)
#include <cuda_runtime.h>
#include <cuda_fp16.h>
#include <math.h>
#include <stdint.h>

#define T_SEQ 2048
#define HID 4096
#define NH 32
#define Q_LORA 1536
#define KV_LORA 512
#define D_NOPE 128
#define D_ROPE 64
#define D_QK 192
#define D_V 128
#define KV_TOT 576
#define NQKVA 2112           // Q_LORA + KV_TOT combined-N
#define NPERSIST 296         // 148 SMs x 2 CTAs

typedef __half fp16;

// ---------------- scratch (static device globals, fp16 pairs) ----------------
__device__ fp16 g_hid_h[(size_t)T_SEQ * HID],        g_hid_l[(size_t)T_SEQ * HID];
__device__ fp16 g_wqakva_h[(size_t)HID * NQKVA],     g_wqakva_l[(size_t)HID * NQKVA];
__device__ fp16 g_wqb_h[(size_t)Q_LORA * NH * D_QK], g_wqb_l[(size_t)Q_LORA * NH * D_QK];
__device__ fp16 g_wuk_h[(size_t)KV_LORA * NH * D_NOPE], g_wuk_l[(size_t)KV_LORA * NH * D_NOPE];
__device__ fp16 g_wuv_h[(size_t)KV_LORA * NH * D_V], g_wuv_l[(size_t)KV_LORA * NH * D_V];
__device__ fp16 g_wo_h[(size_t)NH * D_V * HID],      g_wo_l[(size_t)NH * D_V * HID];

__device__ float g_qckva[(size_t)T_SEQ * NQKVA];     // [qc | kva] fp32
__device__ fp16  g_qc_h[(size_t)T_SEQ * Q_LORA],     g_qc_l[(size_t)T_SEQ * Q_LORA];
__device__ fp16  g_q_h[(size_t)T_SEQ * NH * D_QK],   g_q_l[(size_t)T_SEQ * NH * D_QK];
__device__ fp16  g_keff_h[(size_t)T_SEQ * KV_TOT],   g_keff_l[(size_t)T_SEQ * KV_TOT];
__device__ fp16  g_k_h[(size_t)NH * T_SEQ * D_QK],   g_k_l[(size_t)NH * T_SEQ * D_QK];
__device__ fp16  g_v_h[(size_t)NH * T_SEQ * D_V],    g_v_l[(size_t)NH * T_SEQ * D_V];
__device__ float g_scores[(size_t)NH * T_SEQ * T_SEQ];
__device__ fp16  g_probs_h[(size_t)NH * T_SEQ * T_SEQ], g_probs_l[(size_t)NH * T_SEQ * T_SEQ];
__device__ fp16  g_ov_h[(size_t)T_SEQ * NH * D_V],   g_ov_l[(size_t)T_SEQ * NH * D_V];

// ---------------- asm helpers -------------------------------------------------
__device__ __forceinline__ uint32_t smem_u32(const void* p) {
    return (uint32_t)__cvta_generic_to_shared(p);
}
__device__ __forceinline__ void ldm_x4(uint32_t r[4], uint32_t a) {
    asm volatile("ldmatrix.sync.aligned.m8n8.x4.shared.b16 {%0,%1,%2,%3}, [%4];\n"
                 : "=r"(r[0]), "=r"(r[1]), "=r"(r[2]), "=r"(r[3]) : "r"(a));
}
__device__ __forceinline__ void ldm_x4_t(uint32_t r[4], uint32_t a) {
    asm volatile("ldmatrix.sync.aligned.m8n8.x4.trans.shared.b16 {%0,%1,%2,%3}, [%4];\n"
                 : "=r"(r[0]), "=r"(r[1]), "=r"(r[2]), "=r"(r[3]) : "r"(a));
}
__device__ __forceinline__ void mma16816(float c[4], const uint32_t a[4], const uint32_t b[2]) {
    asm volatile(
        "mma.sync.aligned.m16n8k16.row.col.f32.f16.f16.f32 "
        "{%0,%1,%2,%3}, {%4,%5,%6,%7}, {%8,%9}, {%0,%1,%2,%3};\n"
        : "+f"(c[0]), "+f"(c[1]), "+f"(c[2]), "+f"(c[3])
        : "r"(a[0]), "r"(a[1]), "r"(a[2]), "r"(a[3]), "r"(b[0]), "r"(b[1]));
}
__device__ __forceinline__ void cp16(void* dst, const void* src, bool pred) {
    uint32_t d = smem_u32(dst);
    int sz = pred ? 16 : 0;
    asm volatile("cp.async.cg.shared.global [%0], [%1], 16, %2;\n"
                 :: "r"(d), "l"(src), "r"(sz));
}
__device__ __forceinline__ void cp_commit() { asm volatile("cp.async.commit_group;\n"); }
__device__ __forceinline__ void cp_wait0()  { asm volatile("cp.async.wait_group 0;\n"); }

__device__ __forceinline__ void split2(float v, fp16& h, fp16& l) {
    h = __float2half_rn(v);
    l = __float2half_rn(v - __half2float(h));
}
__device__ __forceinline__ uint32_t pack2(fp16 a, fp16 b) {
    union { uint32_t u; fp16 v[2]; } x;
    x.v[0] = a; x.v[1] = b;
    return x.u;
}

// ---------------- persistent pipelined split-fp16 tensor-core GEMM -----------
// 128 threads, 4 warps, 64x64 warp tiles; BM=BN=128, BK=32; 2-stage cp.async.
// PERSISTENT: grid = min(tiles, 296); each CTA loops tiles with stride gridDim
// (flattens wave quantization; causal-skip tiles are cheap `continue`s).
// NTERMS=3: hh+hl+lh. NTERMS=2: hh+hl (A-lo never loaded).
// op(B)=B row-major [K,N] if !TRANSB; op(B)=B^T (B row-major [N,K]) if TRANSB.
// M % 128 == 0, K % 32 == 0; N masked per 8-col groups.
// OUT_MODE 0: fp32 C.  OUT_MODE 1: fp16 hi/lo pair (Ch, Cl).
template <int NTERMS, bool TRANSB, bool CAUSAL_SKIP, bool CAUSAL_K, int OUT_MODE>
__global__ __launch_bounds__(128, 2)
void mma_gemm(int M, int N, int K, int batch,
              const fp16* __restrict__ gAh, const fp16* __restrict__ gAl, int lda, long long sA,
              const fp16* __restrict__ gBh, const fp16* __restrict__ gBl, int ldb, long long sB,
              float* __restrict__ gCf, fp16* __restrict__ gCh, fp16* __restrict__ gCl,
              int ldc, long long sC)
{
    constexpr int BM = 128, BN = 128, BK = 32;
    constexpr int ALD = 40;
    constexpr int BLD = TRANSB ? 40 : 136;
    constexpr int A_ST = BM * ALD;
    constexpr int B_ST = TRANSB ? (BN * 40) : (BK * 136);

    extern __shared__ __align__(16) char smem_raw[];
    fp16* As_h = (fp16*)smem_raw;
    fp16* As_l = As_h + 2 * A_ST;
    fp16* Bs_h = As_l + (NTERMS == 3 ? 2 * A_ST : 0);
    fp16* Bs_l = Bs_h + 2 * B_ST;

    const int tilesX = (N + BN - 1) / BN;
    const int tilesY = M / BM;
    const int total = tilesX * tilesY * batch;

    const int tid = threadIdx.x, lane = tid & 31, w = tid >> 5;
    const int wm = (w & 1) * 64, wn = (w >> 1) * 64;

    for (int tix = blockIdx.x; tix < total; tix += gridDim.x) {
        const int bz = tix / (tilesX * tilesY);
        const int rem = tix - bz * tilesX * tilesY;
        const int by = rem / tilesX;
        const int bx = rem - by * tilesX;

        const int m0 = by * BM;
        const int n0 = bx * BN;
        if (CAUSAL_SKIP && n0 >= m0 + BM) continue;

        const fp16* Ah = gAh + bz * sA;
        const fp16* Al = gAl + bz * sA;
        const fp16* Bh = gBh + bz * sB;
        const fp16* Bl = gBl + bz * sB;

        const int Keff = CAUSAL_K ? min(K, m0 + BM) : K;
        const int KT = Keff / BK;

        auto load_stage = [&](int st, int k0) {
            #pragma unroll
            for (int i = 0; i < 4; i++) {
                int idx = tid + i * 128;
                int r = idx >> 2, c = (idx & 3) * 8;
                long long g = (long long)(m0 + r) * lda + k0 + c;
                cp16(As_h + st * A_ST + r * ALD + c, Ah + g, true);
                if (NTERMS == 3)
                    cp16(As_l + st * A_ST + r * ALD + c, Al + g, true);
            }
            if (TRANSB) {
                #pragma unroll
                for (int i = 0; i < 4; i++) {
                    int idx = tid + i * 128;
                    int r = idx >> 2, c = (idx & 3) * 8;
                    bool p = (n0 + r) < N;
                    int rr = p ? (n0 + r) : 0;
                    long long g = (long long)rr * ldb + k0 + c;
                    cp16(Bs_h + st * B_ST + r * BLD + c, Bh + g, p);
                    cp16(Bs_l + st * B_ST + r * BLD + c, Bl + g, p);
                }
            } else {
                #pragma unroll
                for (int i = 0; i < 4; i++) {
                    int idx = tid + i * 128;
                    int r = idx >> 4, c = (idx & 15) * 8;
                    bool p = (n0 + c) < N;
                    int cc = p ? (n0 + c) : 0;
                    long long g = (long long)(k0 + r) * ldb + cc;
                    cp16(Bs_h + st * B_ST + r * BLD + c, Bh + g, p);
                    cp16(Bs_l + st * B_ST + r * BLD + c, Bl + g, p);
                }
            }
        };

        float acc[4][8][4] = {};

        load_stage(0, 0);
        cp_commit();

        for (int kt = 0; kt < KT; kt++) {
            cp_wait0();
            __syncthreads();
            const int st = kt & 1;
            if (kt + 1 < KT) { load_stage(st ^ 1, (kt + 1) * BK); cp_commit(); }

            const fp16* Ath = As_h + st * A_ST;
            const fp16* Atl = As_l + st * A_ST;
            const fp16* Bth = Bs_h + st * B_ST;
            const fp16* Btl = Bs_l + st * B_ST;

            #pragma unroll
            for (int kk = 0; kk < 2; kk++) {
                uint32_t ah[4][4], al[4][4];
                uint32_t bh[8][2], bl[8][2];
                #pragma unroll
                for (int mt = 0; mt < 4; mt++) {
                    int row = wm + mt * 16 + (lane & 15);
                    int col = kk * 16 + (lane >> 4) * 8;
                    ldm_x4(ah[mt], smem_u32(Ath + row * ALD + col));
                    if (NTERMS == 3)
                        ldm_x4(al[mt], smem_u32(Atl + row * ALD + col));
                }
                #pragma unroll
                for (int ntp = 0; ntp < 4; ntp++) {
                    uint32_t bh4[4], bl4[4];
                    const int quad = lane >> 3, li = lane & 7;
                    if (TRANSB) {
                        int row = wn + ntp * 16 + (quad >> 1) * 8 + li;
                        int col = kk * 16 + (quad & 1) * 8;
                        ldm_x4(bh4, smem_u32(Bth + row * BLD + col));
                        ldm_x4(bl4, smem_u32(Btl + row * BLD + col));
                    } else {
                        int row = kk * 16 + (quad & 1) * 8 + li;
                        int col = wn + ntp * 16 + (quad >> 1) * 8;
                        ldm_x4_t(bh4, smem_u32(Bth + row * BLD + col));
                        ldm_x4_t(bl4, smem_u32(Btl + row * BLD + col));
                    }
                    bh[ntp * 2 + 0][0] = bh4[0]; bh[ntp * 2 + 0][1] = bh4[1];
                    bh[ntp * 2 + 1][0] = bh4[2]; bh[ntp * 2 + 1][1] = bh4[3];
                    bl[ntp * 2 + 0][0] = bl4[0]; bl[ntp * 2 + 0][1] = bl4[1];
                    bl[ntp * 2 + 1][0] = bl4[2]; bl[ntp * 2 + 1][1] = bl4[3];
                }
                #pragma unroll
                for (int mt = 0; mt < 4; mt++)
                    #pragma unroll
                    for (int nt = 0; nt < 8; nt++)
                        mma16816(acc[mt][nt], ah[mt], bh[nt]);
                #pragma unroll
                for (int mt = 0; mt < 4; mt++)
                    #pragma unroll
                    for (int nt = 0; nt < 8; nt++)
                        mma16816(acc[mt][nt], ah[mt], bl[nt]);
                if (NTERMS == 3) {
                    #pragma unroll
                    for (int mt = 0; mt < 4; mt++)
                        #pragma unroll
                        for (int nt = 0; nt < 8; nt++)
                            mma16816(acc[mt][nt], al[mt], bh[nt]);
                }
            }
        }

        // ---- epilogue ----
        float* Cf = gCf;  fp16* Ch = gCh;  fp16* Cl = gCl;
        if (OUT_MODE == 0) Cf += bz * sC; else { Ch += bz * sC; Cl += bz * sC; }
        const int g = lane >> 2, tg = lane & 3;
        #pragma unroll
        for (int mt = 0; mt < 4; mt++)
            #pragma unroll
            for (int nt = 0; nt < 8; nt++) {
                int col = n0 + wn + nt * 8 + tg * 2;
                if (col >= N) continue;
                int row = m0 + wm + mt * 16 + g;
                if (OUT_MODE == 0) {
                    *(float2*)(Cf + (long long)row * ldc + col) =
                        make_float2(acc[mt][nt][0], acc[mt][nt][1]);
                    *(float2*)(Cf + (long long)(row + 8) * ldc + col) =
                        make_float2(acc[mt][nt][2], acc[mt][nt][3]);
                } else {
                    fp16 h0, l0, h1, l1;
                    split2(acc[mt][nt][0], h0, l0);
                    split2(acc[mt][nt][1], h1, l1);
                    *(uint32_t*)(Ch + (long long)row * ldc + col) = pack2(h0, h1);
                    *(uint32_t*)(Cl + (long long)row * ldc + col) = pack2(l0, l1);
                    split2(acc[mt][nt][2], h0, l0);
                    split2(acc[mt][nt][3], h1, l1);
                    *(uint32_t*)(Ch + (long long)(row + 8) * ldc + col) = pack2(h0, h1);
                    *(uint32_t*)(Cl + (long long)(row + 8) * ldc + col) = pack2(l0, l1);
                }
            }
        __syncthreads();   // all warps done with smem before next tile's loads
    }
}

// ---------------- split fp32 -> fp16 hi/lo (contiguous) ----------------------
__global__ void split_kernel(const float4* __restrict__ x, fp16* __restrict__ h,
                             fp16* __restrict__ l, int n4)
{
    int i = blockIdx.x * 256 + threadIdx.x;
    if (i >= n4) return;
    float4 v = x[i];
    fp16 h0, h1, h2, h3, l0, l1, l2, l3;
    split2(v.x, h0, l0); split2(v.y, h1, l1);
    split2(v.z, h2, l2); split2(v.w, h3, l3);
    *(uint32_t*)(h + (size_t)i * 4)     = pack2(h0, h1);
    *(uint32_t*)(h + (size_t)i * 4 + 2) = pack2(h2, h3);
    *(uint32_t*)(l + (size_t)i * 4)     = pack2(l0, l1);
    *(uint32_t*)(l + (size_t)i * 4 + 2) = pack2(l2, l3);
}

// ---------------- split fp32 -> fp16 hi/lo into strided dst ------------------
__global__ void split_pad_kernel(const float* __restrict__ x, fp16* __restrict__ h,
                                 fp16* __restrict__ l, int rows, int cols,
                                 int ldo, int coloff)
{
    int i = blockIdx.x * 256 + threadIdx.x;
    int n4 = rows * cols / 4;
    if (i >= n4) return;
    int e = i * 4;
    int r = e / cols, c = e - r * cols;
    float4 v = *(const float4*)(x + (size_t)r * cols + c);
    fp16 h0, h1, h2, h3, l0, l1, l2, l3;
    split2(v.x, h0, l0); split2(v.y, h1, l1);
    split2(v.z, h2, l2); split2(v.w, h3, l3);
    size_t o = (size_t)r * ldo + coloff + c;
    *(uint32_t*)(h + o)     = pack2(h0, h1);
    *(uint32_t*)(h + o + 2) = pack2(h2, h3);
    *(uint32_t*)(l + o)     = pack2(l0, l1);
    *(uint32_t*)(l + o + 2) = pack2(l2, l3);
}

// ---------------- RMSNorm fp32 (strided) -> fp16 hi/lo -----------------------
__global__ void rmsnorm_split_kernel(const float* __restrict__ x, int ldx,
                                     const float* __restrict__ scale,
                                     fp16* __restrict__ oh, fp16* __restrict__ ol, int ncols)
{
    const int t = blockIdx.x;
    const float* row = x + (long long)t * ldx;
    __shared__ float red[256];
    float s = 0.f;
    for (int i = threadIdx.x; i < ncols; i += 256) { float v = row[i]; s += v * v; }
    red[threadIdx.x] = s; __syncthreads();
    for (int o = 128; o > 0; o >>= 1) {
        if (threadIdx.x < o) red[threadIdx.x] += red[threadIdx.x + o];
        __syncthreads();
    }
    float inv = rsqrtf(red[0] / (float)ncols + 1e-6f);
    for (int i = threadIdx.x; i < ncols; i += 256) {
        fp16 h, l;
        split2(row[i] * inv * scale[i], h, l);
        oh[(long long)t * ncols + i] = h;
        ol[(long long)t * ncols + i] = l;
    }
}

// ---------------- KV post: RMSNorm(compressed) + RoPE(k_rope) ----------------
__global__ void kv_post_kernel(const float* __restrict__ qckva, const float* __restrict__ kv_scale,
                               const int* __restrict__ positions,
                               fp16* __restrict__ kh, fp16* __restrict__ kl)
{
    const int t = blockIdx.x;
    const float* row = qckva + (long long)t * NQKVA + Q_LORA;   // kva slice
    fp16* oh = kh + (long long)t * KV_TOT;
    fp16* ol = kl + (long long)t * KV_TOT;
    __shared__ float red[256];
    float s = 0.f;
    for (int i = threadIdx.x; i < KV_LORA; i += 256) { float v = row[i]; s += v * v; }
    red[threadIdx.x] = s; __syncthreads();
    for (int o = 128; o > 0; o >>= 1) {
        if (threadIdx.x < o) red[threadIdx.x] += red[threadIdx.x + o];
        __syncthreads();
    }
    float inv = rsqrtf(red[0] / (float)KV_LORA + 1e-6f);
    for (int i = threadIdx.x; i < KV_LORA; i += 256) {
        fp16 h, l;
        split2(row[i] * inv * kv_scale[i], h, l);
        oh[i] = h; ol[i] = l;
    }
    if (threadIdx.x < D_ROPE / 2) {
        int i = threadIdx.x;
        float p = (float)positions[t];
        float freq = powf(10000.f, -(float)(2 * i) / (float)D_ROPE);
        float sn, cs;
        sincosf(p * freq, &sn, &cs);
        float x0 = row[KV_LORA + 2 * i], x1 = row[KV_LORA + 2 * i + 1];
        fp16 h, l;
        split2(x0 * cs - x1 * sn, h, l); oh[KV_LORA + 2 * i] = h;     ol[KV_LORA + 2 * i] = l;
        split2(x0 * sn + x1 * cs, h, l); oh[KV_LORA + 2 * i + 1] = h; ol[KV_LORA + 2 * i + 1] = l;
    }
}

// ---------------- Q RoPE in place on q[t][h][128:192] -------------------------
__global__ void q_rope_kernel(fp16* __restrict__ qh, fp16* __restrict__ ql,
                              const int* __restrict__ positions)
{
    const int t = blockIdx.x;
    const int h = threadIdx.x >> 5;
    const int i = threadIdx.x & 31;
    float p = (float)positions[t];
    float freq = powf(10000.f, -(float)(2 * i) / (float)D_ROPE);
    float sn, cs;
    sincosf(p * freq, &sn, &cs);
    long long a = (long long)t * (NH * D_QK) + h * D_QK + D_NOPE;
    float x0 = __half2float(qh[a + 2 * i]) + __half2float(ql[a + 2 * i]);
    float x1 = __half2float(qh[a + 2 * i + 1]) + __half2float(ql[a + 2 * i + 1]);
    fp16 hh, ll;
    split2(x0 * cs - x1 * sn, hh, ll); qh[a + 2 * i] = hh;     ql[a + 2 * i] = ll;
    split2(x0 * sn + x1 * cs, hh, ll); qh[a + 2 * i + 1] = hh; ql[a + 2 * i + 1] = ll;
}

// ---------------- broadcast k_rope into k[h][s][128:192] ----------------------
__global__ void krope_bcast_kernel(const fp16* __restrict__ keh, const fp16* __restrict__ kel,
                                   fp16* __restrict__ kh, fp16* __restrict__ kl)
{
    const int s = blockIdx.x;
    for (int idx = threadIdx.x; idx < NH * D_ROPE; idx += 256) {
        int h = idx >> 6, i = idx & 63;
        long long dst = (long long)h * T_SEQ * D_QK + (long long)s * D_QK + D_NOPE + i;
        kh[dst] = keh[(long long)s * KV_TOT + KV_LORA + i];
        kl[dst] = kel[(long long)s * KV_TOT + KV_LORA + i];
    }
}

// ---------------- causal softmax: scores fp32 -> probs fp16 hi/lo ------------
__global__ void softmax_probs_kernel(const float* __restrict__ scores,
                                     fp16* __restrict__ ph, fp16* __restrict__ pl)
{
    const int t = blockIdx.x, h = blockIdx.y;
    const long long base = ((long long)h * T_SEQ + t) * T_SEQ;
    const float* row = scores + base;
    const int n = t + 1;
    const float scale = rsqrtf((float)D_QK);
    __shared__ float red[256];
    __shared__ float buf[T_SEQ];

    float m = -3.4e38f;
    for (int i = threadIdx.x; i < n; i += 256) m = fmaxf(m, row[i] * scale);
    red[threadIdx.x] = m; __syncthreads();
    for (int o = 128; o > 0; o >>= 1) {
        if (threadIdx.x < o) red[threadIdx.x] = fmaxf(red[threadIdx.x], red[threadIdx.x + o]);
        __syncthreads();
    }
    const float mx = red[0];
    __syncthreads();

    float sum = 0.f;
    for (int i = threadIdx.x; i < n; i += 256) {
        float e = expf(row[i] * scale - mx);
        buf[i] = e;
        sum += e;
    }
    red[threadIdx.x] = sum; __syncthreads();
    for (int o = 128; o > 0; o >>= 1) {
        if (threadIdx.x < o) red[threadIdx.x] += red[threadIdx.x + o];
        __syncthreads();
    }
    const float inv = 1.f / red[0];
    for (int i = threadIdx.x; i < n; i += 256) {
        fp16 hh, ll;
        split2(buf[i] * inv, hh, ll);
        ph[base + i] = hh; pl[base + i] = ll;
    }
    const int end128 = min(T_SEQ, ((t >> 7) + 1) << 7);
    for (int i = n + threadIdx.x; i < end128; i += 256) {
        ph[base + i] = __float2half_rn(0.f);
        pl[base + i] = __float2half_rn(0.f);
    }
}

// ---------------- host --------------------------------------------------------
static inline dim3 pgrid(int M, int N, int batch) {
    int tiles = ((N + 127) / 128) * (M / 128) * batch;
    return dim3(tiles < NPERSIST ? tiles : NPERSIST);
}

#define SMEM_NT3 81920
#define SMEM_NN2 55296

extern "C" void kernel_launch(void* const* d_in, const int* in_sizes, int n_in,
                              void* d_out, int out_size)
{
    const float* hidden    = (const float*)d_in[0];
    const int*   positions = (const int*)  d_in[1];
    const float* w_qa      = (const float*)d_in[2];
    const float* qa_ln     = (const float*)d_in[3];
    const float* w_qb      = (const float*)d_in[4];
    const float* w_kva     = (const float*)d_in[5];
    const float* kva_ln    = (const float*)d_in[6];
    const float* w_uk      = (const float*)d_in[7];
    const float* w_uv      = (const float*)d_in[8];
    const float* w_o       = (const float*)d_in[9];
    float* out = (float*)d_out;

    fp16 *hid_h, *hid_l, *wqakva_h, *wqakva_l, *wqb_h, *wqb_l;
    fp16 *wuk_h, *wuk_l, *wuv_h, *wuv_l, *wo_h, *wo_l;
    fp16 *qc_h, *qc_l, *q_h, *q_l, *keff_h, *keff_l, *k_h, *k_l;
    fp16 *v_h, *v_l, *probs_h, *probs_l, *ov_h, *ov_l;
    float *qckva, *scores;
    cudaGetSymbolAddress((void**)&hid_h, g_hid_h);     cudaGetSymbolAddress((void**)&hid_l, g_hid_l);
    cudaGetSymbolAddress((void**)&wqakva_h, g_wqakva_h); cudaGetSymbolAddress((void**)&wqakva_l, g_wqakva_l);
    cudaGetSymbolAddress((void**)&wqb_h, g_wqb_h);     cudaGetSymbolAddress((void**)&wqb_l, g_wqb_l);
    cudaGetSymbolAddress((void**)&wuk_h, g_wuk_h);     cudaGetSymbolAddress((void**)&wuk_l, g_wuk_l);
    cudaGetSymbolAddress((void**)&wuv_h, g_wuv_h);     cudaGetSymbolAddress((void**)&wuv_l, g_wuv_l);
    cudaGetSymbolAddress((void**)&wo_h, g_wo_h);       cudaGetSymbolAddress((void**)&wo_l, g_wo_l);
    cudaGetSymbolAddress((void**)&qckva, g_qckva);
    cudaGetSymbolAddress((void**)&qc_h, g_qc_h);       cudaGetSymbolAddress((void**)&qc_l, g_qc_l);
    cudaGetSymbolAddress((void**)&q_h, g_q_h);         cudaGetSymbolAddress((void**)&q_l, g_q_l);
    cudaGetSymbolAddress((void**)&keff_h, g_keff_h);   cudaGetSymbolAddress((void**)&keff_l, g_keff_l);
    cudaGetSymbolAddress((void**)&k_h, g_k_h);         cudaGetSymbolAddress((void**)&k_l, g_k_l);
    cudaGetSymbolAddress((void**)&v_h, g_v_h);         cudaGetSymbolAddress((void**)&v_l, g_v_l);
    cudaGetSymbolAddress((void**)&scores, g_scores);
    cudaGetSymbolAddress((void**)&probs_h, g_probs_h); cudaGetSymbolAddress((void**)&probs_l, g_probs_l);
    cudaGetSymbolAddress((void**)&ov_h, g_ov_h);       cudaGetSymbolAddress((void**)&ov_l, g_ov_l);

    cudaFuncSetAttribute((const void*)mma_gemm<2,false,false,false,0>, cudaFuncAttributeMaxDynamicSharedMemorySize, SMEM_NN2);
    cudaFuncSetAttribute((const void*)mma_gemm<2,false,false,false,1>, cudaFuncAttributeMaxDynamicSharedMemorySize, SMEM_NN2);
    cudaFuncSetAttribute((const void*)mma_gemm<3,true,true,false,0>,   cudaFuncAttributeMaxDynamicSharedMemorySize, SMEM_NT3);
    cudaFuncSetAttribute((const void*)mma_gemm<2,false,false,true,1>,  cudaFuncAttributeMaxDynamicSharedMemorySize, SMEM_NN2);

    auto splitf = [&](const float* src, fp16* h, fp16* l, long long n) {
        int n4 = (int)(n / 4);
        split_kernel<<<(n4 + 255) / 256, 256>>>((const float4*)src, h, l, n4);
    };

    splitf(hidden, hid_h, hid_l, (long long)T_SEQ * HID);            // 1
    // combined weight [w_qa | w_kva] -> [HID][2112]
    {
        int n4 = HID * Q_LORA / 4;
        split_pad_kernel<<<(n4 + 255) / 256, 256>>>(w_qa, wqakva_h, wqakva_l,
                                                    HID, Q_LORA, NQKVA, 0);      // 2
        n4 = HID * KV_TOT / 4;
        split_pad_kernel<<<(n4 + 255) / 256, 256>>>(w_kva, wqakva_h, wqakva_l,
                                                    HID, KV_TOT, NQKVA, Q_LORA); // 3
    }

    // 4) [q_c | kv_a] = hidden @ [w_qa | w_kva] -> fp32 (fp16 2-term, persistent)
    mma_gemm<2,false,false,false,0><<<pgrid(T_SEQ, NQKVA, 1), 128, SMEM_NN2>>>(
        T_SEQ, NQKVA, HID, 1, hid_h, hid_l, HID, 0, wqakva_h, wqakva_l, NQKVA, 0,
        qckva, nullptr, nullptr, NQKVA, 0);

    splitf(w_qb,  wqb_h,  wqb_l,  (long long)Q_LORA * NH * D_QK);
    splitf(w_uk,  wuk_h,  wuk_l,  (long long)KV_LORA * NH * D_NOPE);
    splitf(w_uv,  wuv_h,  wuv_l,  (long long)KV_LORA * NH * D_V);
    splitf(w_o,   wo_h,   wo_l,   (long long)NH * D_V * HID);

    // rmsnorm(q_c) -> qc fp16 hi/lo (strided read from combined buffer)
    rmsnorm_split_kernel<<<T_SEQ, 256>>>(qckva, NQKVA, qa_ln, qc_h, qc_l, Q_LORA);

    // q = q_c @ w_qb (fp16 2-term)
    mma_gemm<2,false,false,false,1><<<pgrid(T_SEQ, NH * D_QK, 1), 128, SMEM_NN2>>>(
        T_SEQ, NH * D_QK, Q_LORA, 1, qc_h, qc_l, Q_LORA, 0, wqb_h, wqb_l, NH * D_QK, 0,
        nullptr, q_h, q_l, NH * D_QK, 0);

    // keff = [rmsnorm(compressed) | rope(k_rope)]
    kv_post_kernel<<<T_SEQ, 256>>>(qckva, kva_ln, positions, keff_h, keff_l);

    // q rope in place
    q_rope_kernel<<<T_SEQ, NH * 32>>>(q_h, q_l, positions);

    // k[h][:, 0:128] = compressed @ w_uk[:,h,:]  (fp16 2-term)
    mma_gemm<2,false,false,false,1><<<pgrid(T_SEQ, D_NOPE, NH), 128, SMEM_NN2>>>(
        T_SEQ, D_NOPE, KV_LORA, NH,
        keff_h, keff_l, KV_TOT, 0,
        wuk_h, wuk_l, NH * D_NOPE, (long long)D_NOPE,
        nullptr, k_h, k_l, D_QK, (long long)T_SEQ * D_QK);

    // k[h][:, 128:192] = k_rope broadcast
    krope_bcast_kernel<<<T_SEQ, 256>>>(keff_h, keff_l, k_h, k_l);

    // v[h] = compressed @ w_uv[:,h,:]  (fp16 2-term)
    mma_gemm<2,false,false,false,1><<<pgrid(T_SEQ, D_V, NH), 128, SMEM_NN2>>>(
        T_SEQ, D_V, KV_LORA, NH,
        keff_h, keff_l, KV_TOT, 0,
        wuv_h, wuv_l, NH * D_V, (long long)D_V,
        nullptr, v_h, v_l, D_V, (long long)T_SEQ * D_V);

    // scores[h] = q[h] @ k[h]^T  (fp16 3-term, causal skip)
    mma_gemm<3,true,true,false,0><<<pgrid(T_SEQ, T_SEQ, NH), 128, SMEM_NT3>>>(
        T_SEQ, T_SEQ, D_QK, NH,
        q_h, q_l, NH * D_QK, (long long)D_QK,
        k_h, k_l, D_QK, (long long)T_SEQ * D_QK,
        scores, nullptr, nullptr, T_SEQ, (long long)T_SEQ * T_SEQ);

    // softmax -> probs fp16 hi/lo
    softmax_probs_kernel<<<dim3(T_SEQ, NH), 256>>>(scores, probs_h, probs_l);

    // ov = probs[h] @ v[h]  (fp16 2-term, causal-K clamp)
    mma_gemm<2,false,false,true,1><<<pgrid(T_SEQ, D_V, NH), 128, SMEM_NN2>>>(
        T_SEQ, D_V, T_SEQ, NH,
        probs_h, probs_l, T_SEQ, (long long)T_SEQ * T_SEQ,
        v_h, v_l, D_V, (long long)T_SEQ * D_V,
        nullptr, ov_h, ov_l, NH * D_V, (long long)D_V);

    // out = ov @ w_o -> fp32  (fp16 2-term)
    mma_gemm<2,false,false,false,0><<<pgrid(T_SEQ, HID, 1), 128, SMEM_NN2>>>(
        T_SEQ, HID, NH * D_V, 1, ov_h, ov_l, NH * D_V, 0, wo_h, wo_l, HID, 0,
        out, nullptr, nullptr, HID, 0);
}

// round 17
// speedup vs baseline: 1.0769x; 1.0769x over previous
#include <cuda_runtime.h>
#include <cuda_fp16.h>
#include <math.h>
#include <stdint.h>

#define T_SEQ 2048
#define HID 4096
#define NH 32
#define Q_LORA 1536
#define KV_LORA 512
#define D_NOPE 128
#define D_ROPE 64
#define D_QK 192
#define D_V 128
#define KV_TOT 576
#define NQKVA 2112           // Q_LORA + KV_TOT combined-N
#define NPERSIST 296         // 148 SMs x 2 CTAs

typedef __half fp16;

// ---------------- scratch (static device globals, fp16 pairs) ----------------
__device__ fp16 g_hid_h[(size_t)T_SEQ * HID],        g_hid_l[(size_t)T_SEQ * HID];
__device__ fp16 g_wqakva_h[(size_t)HID * NQKVA],     g_wqakva_l[(size_t)HID * NQKVA];
__device__ fp16 g_wqb_h[(size_t)Q_LORA * NH * D_QK], g_wqb_l[(size_t)Q_LORA * NH * D_QK];
__device__ fp16 g_wuk_h[(size_t)KV_LORA * NH * D_NOPE], g_wuk_l[(size_t)KV_LORA * NH * D_NOPE];
__device__ fp16 g_wuv_h[(size_t)KV_LORA * NH * D_V], g_wuv_l[(size_t)KV_LORA * NH * D_V];
__device__ fp16 g_wo_h[(size_t)NH * D_V * HID],      g_wo_l[(size_t)NH * D_V * HID];

__device__ float g_qckva[(size_t)T_SEQ * NQKVA];     // [qc | kva] fp32
__device__ fp16  g_qc_h[(size_t)T_SEQ * Q_LORA],     g_qc_l[(size_t)T_SEQ * Q_LORA];
__device__ fp16  g_q_h[(size_t)T_SEQ * NH * D_QK],   g_q_l[(size_t)T_SEQ * NH * D_QK];
__device__ fp16  g_keff_h[(size_t)T_SEQ * KV_TOT],   g_keff_l[(size_t)T_SEQ * KV_TOT];
__device__ fp16  g_k_h[(size_t)NH * T_SEQ * D_QK],   g_k_l[(size_t)NH * T_SEQ * D_QK];
__device__ fp16  g_v_h[(size_t)NH * T_SEQ * D_V],    g_v_l[(size_t)NH * T_SEQ * D_V];
__device__ float g_scores[(size_t)NH * T_SEQ * T_SEQ];
__device__ fp16  g_probs_h[(size_t)NH * T_SEQ * T_SEQ], g_probs_l[(size_t)NH * T_SEQ * T_SEQ];
__device__ fp16  g_ov_h[(size_t)T_SEQ * NH * D_V],   g_ov_l[(size_t)T_SEQ * NH * D_V];

// ---------------- asm helpers -------------------------------------------------
__device__ __forceinline__ uint32_t smem_u32(const void* p) {
    return (uint32_t)__cvta_generic_to_shared(p);
}
__device__ __forceinline__ void ldm_x4(uint32_t r[4], uint32_t a) {
    asm volatile("ldmatrix.sync.aligned.m8n8.x4.shared.b16 {%0,%1,%2,%3}, [%4];\n"
                 : "=r"(r[0]), "=r"(r[1]), "=r"(r[2]), "=r"(r[3]) : "r"(a));
}
__device__ __forceinline__ void ldm_x4_t(uint32_t r[4], uint32_t a) {
    asm volatile("ldmatrix.sync.aligned.m8n8.x4.trans.shared.b16 {%0,%1,%2,%3}, [%4];\n"
                 : "=r"(r[0]), "=r"(r[1]), "=r"(r[2]), "=r"(r[3]) : "r"(a));
}
__device__ __forceinline__ void mma16816(float c[4], const uint32_t a[4], const uint32_t b[2]) {
    asm volatile(
        "mma.sync.aligned.m16n8k16.row.col.f32.f16.f16.f32 "
        "{%0,%1,%2,%3}, {%4,%5,%6,%7}, {%8,%9}, {%0,%1,%2,%3};\n"
        : "+f"(c[0]), "+f"(c[1]), "+f"(c[2]), "+f"(c[3])
        : "r"(a[0]), "r"(a[1]), "r"(a[2]), "r"(a[3]), "r"(b[0]), "r"(b[1]));
}
__device__ __forceinline__ void cp16(void* dst, const void* src, bool pred) {
    uint32_t d = smem_u32(dst);
    int sz = pred ? 16 : 0;
    asm volatile("cp.async.cg.shared.global [%0], [%1], 16, %2;\n"
                 :: "r"(d), "l"(src), "r"(sz));
}
__device__ __forceinline__ void cp_commit() { asm volatile("cp.async.commit_group;\n"); }
__device__ __forceinline__ void cp_wait0()  { asm volatile("cp.async.wait_group 0;\n"); }

__device__ __forceinline__ void split2(float v, fp16& h, fp16& l) {
    h = __float2half_rn(v);
    l = __float2half_rn(v - __half2float(h));
}
__device__ __forceinline__ uint32_t pack2(fp16 a, fp16 b) {
    union { uint32_t u; fp16 v[2]; } x;
    x.v[0] = a; x.v[1] = b;
    return x.u;
}

// ---------------- tile-loop pipelined split-fp16 tensor-core GEMM ------------
// 128 threads, 4 warps, 64x64 warp tiles; BM=BN=128, BK=32; 2-stage cp.async.
// Launched with grid = tiles (loop runs once; HW scheduler balances) OR
// grid = NPERSIST for uniform-work GEMMs (persistent, flattens waves).
// NTERMS=3: hh+hl+lh. NTERMS=2: hh+hl (A-lo never loaded).
// op(B)=B row-major [K,N] if !TRANSB; op(B)=B^T (B row-major [N,K]) if TRANSB.
// M % 128 == 0, K % 32 == 0; N masked per 8-col groups.
// OUT_MODE 0: fp32 C.  OUT_MODE 1: fp16 hi/lo pair (Ch, Cl).
template <int NTERMS, bool TRANSB, bool CAUSAL_SKIP, bool CAUSAL_K, int OUT_MODE>
__global__ __launch_bounds__(128, 2)
void mma_gemm(int M, int N, int K, int batch,
              const fp16* __restrict__ gAh, const fp16* __restrict__ gAl, int lda, long long sA,
              const fp16* __restrict__ gBh, const fp16* __restrict__ gBl, int ldb, long long sB,
              float* __restrict__ gCf, fp16* __restrict__ gCh, fp16* __restrict__ gCl,
              int ldc, long long sC)
{
    constexpr int BM = 128, BN = 128, BK = 32;
    constexpr int ALD = 40;
    constexpr int BLD = TRANSB ? 40 : 136;
    constexpr int A_ST = BM * ALD;
    constexpr int B_ST = TRANSB ? (BN * 40) : (BK * 136);

    extern __shared__ __align__(16) char smem_raw[];
    fp16* As_h = (fp16*)smem_raw;
    fp16* As_l = As_h + 2 * A_ST;
    fp16* Bs_h = As_l + (NTERMS == 3 ? 2 * A_ST : 0);
    fp16* Bs_l = Bs_h + 2 * B_ST;

    const int tilesX = (N + BN - 1) / BN;
    const int tilesY = M / BM;
    const int total = tilesX * tilesY * batch;

    const int tid = threadIdx.x, lane = tid & 31, w = tid >> 5;
    const int wm = (w & 1) * 64, wn = (w >> 1) * 64;

    for (int tix = blockIdx.x; tix < total; tix += gridDim.x) {
        const int bz = tix / (tilesX * tilesY);
        const int rem = tix - bz * tilesX * tilesY;
        const int by = rem / tilesX;
        const int bx = rem - by * tilesX;

        const int m0 = by * BM;
        const int n0 = bx * BN;
        if (CAUSAL_SKIP && n0 >= m0 + BM) continue;

        const fp16* Ah = gAh + bz * sA;
        const fp16* Al = gAl + bz * sA;
        const fp16* Bh = gBh + bz * sB;
        const fp16* Bl = gBl + bz * sB;

        const int Keff = CAUSAL_K ? min(K, m0 + BM) : K;
        const int KT = Keff / BK;

        auto load_stage = [&](int st, int k0) {
            #pragma unroll
            for (int i = 0; i < 4; i++) {
                int idx = tid + i * 128;
                int r = idx >> 2, c = (idx & 3) * 8;
                long long g = (long long)(m0 + r) * lda + k0 + c;
                cp16(As_h + st * A_ST + r * ALD + c, Ah + g, true);
                if (NTERMS == 3)
                    cp16(As_l + st * A_ST + r * ALD + c, Al + g, true);
            }
            if (TRANSB) {
                #pragma unroll
                for (int i = 0; i < 4; i++) {
                    int idx = tid + i * 128;
                    int r = idx >> 2, c = (idx & 3) * 8;
                    bool p = (n0 + r) < N;
                    int rr = p ? (n0 + r) : 0;
                    long long g = (long long)rr * ldb + k0 + c;
                    cp16(Bs_h + st * B_ST + r * BLD + c, Bh + g, p);
                    cp16(Bs_l + st * B_ST + r * BLD + c, Bl + g, p);
                }
            } else {
                #pragma unroll
                for (int i = 0; i < 4; i++) {
                    int idx = tid + i * 128;
                    int r = idx >> 4, c = (idx & 15) * 8;
                    bool p = (n0 + c) < N;
                    int cc = p ? (n0 + c) : 0;
                    long long g = (long long)(k0 + r) * ldb + cc;
                    cp16(Bs_h + st * B_ST + r * BLD + c, Bh + g, p);
                    cp16(Bs_l + st * B_ST + r * BLD + c, Bl + g, p);
                }
            }
        };

        float acc[4][8][4] = {};

        load_stage(0, 0);
        cp_commit();

        for (int kt = 0; kt < KT; kt++) {
            cp_wait0();
            __syncthreads();
            const int st = kt & 1;
            if (kt + 1 < KT) { load_stage(st ^ 1, (kt + 1) * BK); cp_commit(); }

            const fp16* Ath = As_h + st * A_ST;
            const fp16* Atl = As_l + st * A_ST;
            const fp16* Bth = Bs_h + st * B_ST;
            const fp16* Btl = Bs_l + st * B_ST;

            #pragma unroll
            for (int kk = 0; kk < 2; kk++) {
                uint32_t ah[4][4], al[4][4];
                uint32_t bh[8][2], bl[8][2];
                #pragma unroll
                for (int mt = 0; mt < 4; mt++) {
                    int row = wm + mt * 16 + (lane & 15);
                    int col = kk * 16 + (lane >> 4) * 8;
                    ldm_x4(ah[mt], smem_u32(Ath + row * ALD + col));
                    if (NTERMS == 3)
                        ldm_x4(al[mt], smem_u32(Atl + row * ALD + col));
                }
                #pragma unroll
                for (int ntp = 0; ntp < 4; ntp++) {
                    uint32_t bh4[4], bl4[4];
                    const int quad = lane >> 3, li = lane & 7;
                    if (TRANSB) {
                        int row = wn + ntp * 16 + (quad >> 1) * 8 + li;
                        int col = kk * 16 + (quad & 1) * 8;
                        ldm_x4(bh4, smem_u32(Bth + row * BLD + col));
                        ldm_x4(bl4, smem_u32(Btl + row * BLD + col));
                    } else {
                        int row = kk * 16 + (quad & 1) * 8 + li;
                        int col = wn + ntp * 16 + (quad >> 1) * 8;
                        ldm_x4_t(bh4, smem_u32(Bth + row * BLD + col));
                        ldm_x4_t(bl4, smem_u32(Btl + row * BLD + col));
                    }
                    bh[ntp * 2 + 0][0] = bh4[0]; bh[ntp * 2 + 0][1] = bh4[1];
                    bh[ntp * 2 + 1][0] = bh4[2]; bh[ntp * 2 + 1][1] = bh4[3];
                    bl[ntp * 2 + 0][0] = bl4[0]; bl[ntp * 2 + 0][1] = bl4[1];
                    bl[ntp * 2 + 1][0] = bl4[2]; bl[ntp * 2 + 1][1] = bl4[3];
                }
                #pragma unroll
                for (int mt = 0; mt < 4; mt++)
                    #pragma unroll
                    for (int nt = 0; nt < 8; nt++)
                        mma16816(acc[mt][nt], ah[mt], bh[nt]);
                #pragma unroll
                for (int mt = 0; mt < 4; mt++)
                    #pragma unroll
                    for (int nt = 0; nt < 8; nt++)
                        mma16816(acc[mt][nt], ah[mt], bl[nt]);
                if (NTERMS == 3) {
                    #pragma unroll
                    for (int mt = 0; mt < 4; mt++)
                        #pragma unroll
                        for (int nt = 0; nt < 8; nt++)
                            mma16816(acc[mt][nt], al[mt], bh[nt]);
                }
            }
        }

        // ---- epilogue ----
        float* Cf = gCf;  fp16* Ch = gCh;  fp16* Cl = gCl;
        if (OUT_MODE == 0) Cf += bz * sC; else { Ch += bz * sC; Cl += bz * sC; }
        const int g = lane >> 2, tg = lane & 3;
        #pragma unroll
        for (int mt = 0; mt < 4; mt++)
            #pragma unroll
            for (int nt = 0; nt < 8; nt++) {
                int col = n0 + wn + nt * 8 + tg * 2;
                if (col >= N) continue;
                int row = m0 + wm + mt * 16 + g;
                if (OUT_MODE == 0) {
                    *(float2*)(Cf + (long long)row * ldc + col) =
                        make_float2(acc[mt][nt][0], acc[mt][nt][1]);
                    *(float2*)(Cf + (long long)(row + 8) * ldc + col) =
                        make_float2(acc[mt][nt][2], acc[mt][nt][3]);
                } else {
                    fp16 h0, l0, h1, l1;
                    split2(acc[mt][nt][0], h0, l0);
                    split2(acc[mt][nt][1], h1, l1);
                    *(uint32_t*)(Ch + (long long)row * ldc + col) = pack2(h0, h1);
                    *(uint32_t*)(Cl + (long long)row * ldc + col) = pack2(l0, l1);
                    split2(acc[mt][nt][2], h0, l0);
                    split2(acc[mt][nt][3], h1, l1);
                    *(uint32_t*)(Ch + (long long)(row + 8) * ldc + col) = pack2(h0, h1);
                    *(uint32_t*)(Cl + (long long)(row + 8) * ldc + col) = pack2(l0, l1);
                }
            }
        __syncthreads();   // smem safe before next tile's loads
    }
}

// ---------------- split fp32 -> fp16 hi/lo (contiguous) ----------------------
__global__ void split_kernel(const float4* __restrict__ x, fp16* __restrict__ h,
                             fp16* __restrict__ l, int n4)
{
    int i = blockIdx.x * 256 + threadIdx.x;
    if (i >= n4) return;
    float4 v = x[i];
    fp16 h0, h1, h2, h3, l0, l1, l2, l3;
    split2(v.x, h0, l0); split2(v.y, h1, l1);
    split2(v.z, h2, l2); split2(v.w, h3, l3);
    *(uint32_t*)(h + (size_t)i * 4)     = pack2(h0, h1);
    *(uint32_t*)(h + (size_t)i * 4 + 2) = pack2(h2, h3);
    *(uint32_t*)(l + (size_t)i * 4)     = pack2(l0, l1);
    *(uint32_t*)(l + (size_t)i * 4 + 2) = pack2(l2, l3);
}

// ---------------- split fp32 -> fp16 hi/lo into strided dst ------------------
__global__ void split_pad_kernel(const float* __restrict__ x, fp16* __restrict__ h,
                                 fp16* __restrict__ l, int rows, int cols,
                                 int ldo, int coloff)
{
    int i = blockIdx.x * 256 + threadIdx.x;
    int n4 = rows * cols / 4;
    if (i >= n4) return;
    int e = i * 4;
    int r = e / cols, c = e - r * cols;
    float4 v = *(const float4*)(x + (size_t)r * cols + c);
    fp16 h0, h1, h2, h3, l0, l1, l2, l3;
    split2(v.x, h0, l0); split2(v.y, h1, l1);
    split2(v.z, h2, l2); split2(v.w, h3, l3);
    size_t o = (size_t)r * ldo + coloff + c;
    *(uint32_t*)(h + o)     = pack2(h0, h1);
    *(uint32_t*)(h + o + 2) = pack2(h2, h3);
    *(uint32_t*)(l + o)     = pack2(l0, l1);
    *(uint32_t*)(l + o + 2) = pack2(l2, l3);
}

// ---------------- RMSNorm fp32 (strided) -> fp16 hi/lo -----------------------
__global__ void rmsnorm_split_kernel(const float* __restrict__ x, int ldx,
                                     const float* __restrict__ scale,
                                     fp16* __restrict__ oh, fp16* __restrict__ ol, int ncols)
{
    const int t = blockIdx.x;
    const float* row = x + (long long)t * ldx;
    __shared__ float red[256];
    float s = 0.f;
    for (int i = threadIdx.x; i < ncols; i += 256) { float v = row[i]; s += v * v; }
    red[threadIdx.x] = s; __syncthreads();
    for (int o = 128; o > 0; o >>= 1) {
        if (threadIdx.x < o) red[threadIdx.x] += red[threadIdx.x + o];
        __syncthreads();
    }
    float inv = rsqrtf(red[0] / (float)ncols + 1e-6f);
    for (int i = threadIdx.x; i < ncols; i += 256) {
        fp16 h, l;
        split2(row[i] * inv * scale[i], h, l);
        oh[(long long)t * ncols + i] = h;
        ol[(long long)t * ncols + i] = l;
    }
}

// ---------------- KV post: RMSNorm(compressed) + RoPE(k_rope) ----------------
__global__ void kv_post_kernel(const float* __restrict__ qckva, const float* __restrict__ kv_scale,
                               const int* __restrict__ positions,
                               fp16* __restrict__ kh, fp16* __restrict__ kl)
{
    const int t = blockIdx.x;
    const float* row = qckva + (long long)t * NQKVA + Q_LORA;
    fp16* oh = kh + (long long)t * KV_TOT;
    fp16* ol = kl + (long long)t * KV_TOT;
    __shared__ float red[256];
    float s = 0.f;
    for (int i = threadIdx.x; i < KV_LORA; i += 256) { float v = row[i]; s += v * v; }
    red[threadIdx.x] = s; __syncthreads();
    for (int o = 128; o > 0; o >>= 1) {
        if (threadIdx.x < o) red[threadIdx.x] += red[threadIdx.x + o];
        __syncthreads();
    }
    float inv = rsqrtf(red[0] / (float)KV_LORA + 1e-6f);
    for (int i = threadIdx.x; i < KV_LORA; i += 256) {
        fp16 h, l;
        split2(row[i] * inv * kv_scale[i], h, l);
        oh[i] = h; ol[i] = l;
    }
    if (threadIdx.x < D_ROPE / 2) {
        int i = threadIdx.x;
        float p = (float)positions[t];
        float freq = powf(10000.f, -(float)(2 * i) / (float)D_ROPE);
        float sn, cs;
        sincosf(p * freq, &sn, &cs);
        float x0 = row[KV_LORA + 2 * i], x1 = row[KV_LORA + 2 * i + 1];
        fp16 h, l;
        split2(x0 * cs - x1 * sn, h, l); oh[KV_LORA + 2 * i] = h;     ol[KV_LORA + 2 * i] = l;
        split2(x0 * sn + x1 * cs, h, l); oh[KV_LORA + 2 * i + 1] = h; ol[KV_LORA + 2 * i + 1] = l;
    }
}

// ---------------- Q RoPE in place on q[t][h][128:192] -------------------------
__global__ void q_rope_kernel(fp16* __restrict__ qh, fp16* __restrict__ ql,
                              const int* __restrict__ positions)
{
    const int t = blockIdx.x;
    const int h = threadIdx.x >> 5;
    const int i = threadIdx.x & 31;
    float p = (float)positions[t];
    float freq = powf(10000.f, -(float)(2 * i) / (float)D_ROPE);
    float sn, cs;
    sincosf(p * freq, &sn, &cs);
    long long a = (long long)t * (NH * D_QK) + h * D_QK + D_NOPE;
    float x0 = __half2float(qh[a + 2 * i]) + __half2float(ql[a + 2 * i]);
    float x1 = __half2float(qh[a + 2 * i + 1]) + __half2float(ql[a + 2 * i + 1]);
    fp16 hh, ll;
    split2(x0 * cs - x1 * sn, hh, ll); qh[a + 2 * i] = hh;     ql[a + 2 * i] = ll;
    split2(x0 * sn + x1 * cs, hh, ll); qh[a + 2 * i + 1] = hh; ql[a + 2 * i + 1] = ll;
}

// ---------------- broadcast k_rope into k[h][s][128:192] ----------------------
__global__ void krope_bcast_kernel(const fp16* __restrict__ keh, const fp16* __restrict__ kel,
                                   fp16* __restrict__ kh, fp16* __restrict__ kl)
{
    const int s = blockIdx.x;
    for (int idx = threadIdx.x; idx < NH * D_ROPE; idx += 256) {
        int h = idx >> 6, i = idx & 63;
        long long dst = (long long)h * T_SEQ * D_QK + (long long)s * D_QK + D_NOPE + i;
        kh[dst] = keh[(long long)s * KV_TOT + KV_LORA + i];
        kl[dst] = kel[(long long)s * KV_TOT + KV_LORA + i];
    }
}

// ---------------- causal softmax: scores fp32 -> probs fp16 hi/lo ------------
__global__ void softmax_probs_kernel(const float* __restrict__ scores,
                                     fp16* __restrict__ ph, fp16* __restrict__ pl)
{
    const int t = blockIdx.x, h = blockIdx.y;
    const long long base = ((long long)h * T_SEQ + t) * T_SEQ;
    const float* row = scores + base;
    const int n = t + 1;
    const float scale = rsqrtf((float)D_QK);
    __shared__ float red[256];
    __shared__ float buf[T_SEQ];

    float m = -3.4e38f;
    for (int i = threadIdx.x; i < n; i += 256) m = fmaxf(m, row[i] * scale);
    red[threadIdx.x] = m; __syncthreads();
    for (int o = 128; o > 0; o >>= 1) {
        if (threadIdx.x < o) red[threadIdx.x] = fmaxf(red[threadIdx.x], red[threadIdx.x + o]);
        __syncthreads();
    }
    const float mx = red[0];
    __syncthreads();

    float sum = 0.f;
    for (int i = threadIdx.x; i < n; i += 256) {
        float e = expf(row[i] * scale - mx);
        buf[i] = e;
        sum += e;
    }
    red[threadIdx.x] = sum; __syncthreads();
    for (int o = 128; o > 0; o >>= 1) {
        if (threadIdx.x < o) red[threadIdx.x] += red[threadIdx.x + o];
        __syncthreads();
    }
    const float inv = 1.f / red[0];
    for (int i = threadIdx.x; i < n; i += 256) {
        fp16 hh, ll;
        split2(buf[i] * inv, hh, ll);
        ph[base + i] = hh; pl[base + i] = ll;
    }
    const int end128 = min(T_SEQ, ((t >> 7) + 1) << 7);
    for (int i = n + threadIdx.x; i < end128; i += 256) {
        ph[base + i] = __float2half_rn(0.f);
        pl[base + i] = __float2half_rn(0.f);
    }
}

// ---------------- host --------------------------------------------------------
static inline dim3 fullgrid(int M, int N, int batch) {
    return dim3(((N + 127) / 128) * (M / 128) * batch);   // loop runs once
}

#define SMEM_NT3 81920
#define SMEM_NN2 55296

extern "C" void kernel_launch(void* const* d_in, const int* in_sizes, int n_in,
                              void* d_out, int out_size)
{
    const float* hidden    = (const float*)d_in[0];
    const int*   positions = (const int*)  d_in[1];
    const float* w_qa      = (const float*)d_in[2];
    const float* qa_ln     = (const float*)d_in[3];
    const float* w_qb      = (const float*)d_in[4];
    const float* w_kva     = (const float*)d_in[5];
    const float* kva_ln    = (const float*)d_in[6];
    const float* w_uk      = (const float*)d_in[7];
    const float* w_uv      = (const float*)d_in[8];
    const float* w_o       = (const float*)d_in[9];
    float* out = (float*)d_out;

    fp16 *hid_h, *hid_l, *wqakva_h, *wqakva_l, *wqb_h, *wqb_l;
    fp16 *wuk_h, *wuk_l, *wuv_h, *wuv_l, *wo_h, *wo_l;
    fp16 *qc_h, *qc_l, *q_h, *q_l, *keff_h, *keff_l, *k_h, *k_l;
    fp16 *v_h, *v_l, *probs_h, *probs_l, *ov_h, *ov_l;
    float *qckva, *scores;
    cudaGetSymbolAddress((void**)&hid_h, g_hid_h);     cudaGetSymbolAddress((void**)&hid_l, g_hid_l);
    cudaGetSymbolAddress((void**)&wqakva_h, g_wqakva_h); cudaGetSymbolAddress((void**)&wqakva_l, g_wqakva_l);
    cudaGetSymbolAddress((void**)&wqb_h, g_wqb_h);     cudaGetSymbolAddress((void**)&wqb_l, g_wqb_l);
    cudaGetSymbolAddress((void**)&wuk_h, g_wuk_h);     cudaGetSymbolAddress((void**)&wuk_l, g_wuk_l);
    cudaGetSymbolAddress((void**)&wuv_h, g_wuv_h);     cudaGetSymbolAddress((void**)&wuv_l, g_wuv_l);
    cudaGetSymbolAddress((void**)&wo_h, g_wo_h);       cudaGetSymbolAddress((void**)&wo_l, g_wo_l);
    cudaGetSymbolAddress((void**)&qckva, g_qckva);
    cudaGetSymbolAddress((void**)&qc_h, g_qc_h);       cudaGetSymbolAddress((void**)&qc_l, g_qc_l);
    cudaGetSymbolAddress((void**)&q_h, g_q_h);         cudaGetSymbolAddress((void**)&q_l, g_q_l);
    cudaGetSymbolAddress((void**)&keff_h, g_keff_h);   cudaGetSymbolAddress((void**)&keff_l, g_keff_l);
    cudaGetSymbolAddress((void**)&k_h, g_k_h);         cudaGetSymbolAddress((void**)&k_l, g_k_l);
    cudaGetSymbolAddress((void**)&v_h, g_v_h);         cudaGetSymbolAddress((void**)&v_l, g_v_l);
    cudaGetSymbolAddress((void**)&scores, g_scores);
    cudaGetSymbolAddress((void**)&probs_h, g_probs_h); cudaGetSymbolAddress((void**)&probs_l, g_probs_l);
    cudaGetSymbolAddress((void**)&ov_h, g_ov_h);       cudaGetSymbolAddress((void**)&ov_l, g_ov_l);

    cudaFuncSetAttribute((const void*)mma_gemm<2,false,false,false,0>, cudaFuncAttributeMaxDynamicSharedMemorySize, SMEM_NN2);
    cudaFuncSetAttribute((const void*)mma_gemm<2,false,false,false,1>, cudaFuncAttributeMaxDynamicSharedMemorySize, SMEM_NN2);
    cudaFuncSetAttribute((const void*)mma_gemm<3,true,true,false,0>,   cudaFuncAttributeMaxDynamicSharedMemorySize, SMEM_NT3);
    cudaFuncSetAttribute((const void*)mma_gemm<2,false,false,true,1>,  cudaFuncAttributeMaxDynamicSharedMemorySize, SMEM_NN2);

    auto splitf = [&](const float* src, fp16* h, fp16* l, long long n) {
        int n4 = (int)(n / 4);
        split_kernel<<<(n4 + 255) / 256, 256>>>((const float4*)src, h, l, n4);
    };

    splitf(hidden, hid_h, hid_l, (long long)T_SEQ * HID);            // 1
    {
        int n4 = HID * Q_LORA / 4;
        split_pad_kernel<<<(n4 + 255) / 256, 256>>>(w_qa, wqakva_h, wqakva_l,
                                                    HID, Q_LORA, NQKVA, 0);      // 2
        n4 = HID * KV_TOT / 4;
        split_pad_kernel<<<(n4 + 255) / 256, 256>>>(w_kva, wqakva_h, wqakva_l,
                                                    HID, KV_TOT, NQKVA, Q_LORA); // 3
    }

    // 4) [q_c | kv_a] = hidden @ [w_qa | w_kva]  (persistent: 272 uniform tiles)
    mma_gemm<2,false,false,false,0><<<dim3(272), 128, SMEM_NN2>>>(
        T_SEQ, NQKVA, HID, 1, hid_h, hid_l, HID, 0, wqakva_h, wqakva_l, NQKVA, 0,
        qckva, nullptr, nullptr, NQKVA, 0);

    splitf(w_qb,  wqb_h,  wqb_l,  (long long)Q_LORA * NH * D_QK);
    splitf(w_uk,  wuk_h,  wuk_l,  (long long)KV_LORA * NH * D_NOPE);
    splitf(w_uv,  wuv_h,  wuv_l,  (long long)KV_LORA * NH * D_V);
    splitf(w_o,   wo_h,   wo_l,   (long long)NH * D_V * HID);

    // rmsnorm(q_c) -> qc fp16 hi/lo
    rmsnorm_split_kernel<<<T_SEQ, 256>>>(qckva, NQKVA, qa_ln, qc_h, qc_l, Q_LORA);

    // q = q_c @ w_qb (full grid)
    mma_gemm<2,false,false,false,1><<<fullgrid(T_SEQ, NH * D_QK, 1), 128, SMEM_NN2>>>(
        T_SEQ, NH * D_QK, Q_LORA, 1, qc_h, qc_l, Q_LORA, 0, wqb_h, wqb_l, NH * D_QK, 0,
        nullptr, q_h, q_l, NH * D_QK, 0);

    // keff = [rmsnorm(compressed) | rope(k_rope)]
    kv_post_kernel<<<T_SEQ, 256>>>(qckva, kva_ln, positions, keff_h, keff_l);

    // q rope in place
    q_rope_kernel<<<T_SEQ, NH * 32>>>(q_h, q_l, positions);

    // k[h][:, 0:128] = compressed @ w_uk[:,h,:]  (full grid)
    mma_gemm<2,false,false,false,1><<<fullgrid(T_SEQ, D_NOPE, NH), 128, SMEM_NN2>>>(
        T_SEQ, D_NOPE, KV_LORA, NH,
        keff_h, keff_l, KV_TOT, 0,
        wuk_h, wuk_l, NH * D_NOPE, (long long)D_NOPE,
        nullptr, k_h, k_l, D_QK, (long long)T_SEQ * D_QK);

    // k[h][:, 128:192] = k_rope broadcast
    krope_bcast_kernel<<<T_SEQ, 256>>>(keff_h, keff_l, k_h, k_l);

    // v[h] = compressed @ w_uv[:,h,:]  (full grid)
    mma_gemm<2,false,false,false,1><<<fullgrid(T_SEQ, D_V, NH), 128, SMEM_NN2>>>(
        T_SEQ, D_V, KV_LORA, NH,
        keff_h, keff_l, KV_TOT, 0,
        wuv_h, wuv_l, NH * D_V, (long long)D_V,
        nullptr, v_h, v_l, D_V, (long long)T_SEQ * D_V);

    // scores[h] = q[h] @ k[h]^T  (fp16 3-term, causal skip, full grid)
    mma_gemm<3,true,true,false,0><<<fullgrid(T_SEQ, T_SEQ, NH), 128, SMEM_NT3>>>(
        T_SEQ, T_SEQ, D_QK, NH,
        q_h, q_l, NH * D_QK, (long long)D_QK,
        k_h, k_l, D_QK, (long long)T_SEQ * D_QK,
        scores, nullptr, nullptr, T_SEQ, (long long)T_SEQ * T_SEQ);

    // softmax -> probs fp16 hi/lo
    softmax_probs_kernel<<<dim3(T_SEQ, NH), 256>>>(scores, probs_h, probs_l);

    // ov = probs[h] @ v[h]  (fp16 2-term, causal-K clamp, full grid)
    mma_gemm<2,false,false,true,1><<<fullgrid(T_SEQ, D_V, NH), 128, SMEM_NN2>>>(
        T_SEQ, D_V, T_SEQ, NH,
        probs_h, probs_l, T_SEQ, (long long)T_SEQ * T_SEQ,
        v_h, v_l, D_V, (long long)T_SEQ * D_V,
        nullptr, ov_h, ov_l, NH * D_V, (long long)D_V);

    // out = ov @ w_o -> fp32  (full grid)
    mma_gemm<2,false,false,false,0><<<fullgrid(T_SEQ, HID, 1), 128, SMEM_NN2>>>(
        T_SEQ, HID, NH * D_V, 1, ov_h, ov_l, NH * D_V, 0, wo_h, wo_l, HID, 0,
        out, nullptr, nullptr, HID, 0);
}